// round 6
// baseline (speedup 1.0000x reference)
#include <cuda_runtime.h>

#define B_N   32768
#define FIN   64
#define HID   32
#define E_N   25
#define HG    96
#define BAND_HG 8
#define NBAND 12
#define MB    224      // 8 heads * 28 (16B-aligned head base)
#define EPD_STRIDE 65  // u64 row stride for e-tile
#define NT    8        // row-tiles per kernC block

typedef unsigned long long u64;

// scratch (static device globals — no allocation)
__device__ float g_h2[B_N * HID];          // 4 MB intermediate
__device__ float g_part[1024][2 * HID];    // per-block BN partial sums
__device__ float g_scale[HID];
__device__ float g_shift[HID];

__device__ __forceinline__ float selu_f(float x) {
    float p = 1.0507009873554805f * x;
    float n = 1.7580993408473766f * (__expf(x) - 1.0f);  // lambda*alpha
    return x > 0.0f ? p : n;
}
__device__ __forceinline__ u64 pk2(float lo, float hi) {
    u64 r;
    asm("mov.b64 %0, {%1,%2};" : "=l"(r)
        : "r"(__float_as_uint(lo)), "r"(__float_as_uint(hi)));
    return r;
}
__device__ __forceinline__ void upk2(u64 v, float& lo, float& hi) {
    unsigned int a, b;
    asm("mov.b64 {%0,%1}, %2;" : "=r"(a), "=r"(b) : "l"(v));
    lo = __uint_as_float(a); hi = __uint_as_float(b);
}
// packed fp32x2 FMA (FFMA2) — only reachable via PTX
#define FFMA2(d, a, b) asm("fma.rn.f32x2 %0, %1, %2, %0;" : "+l"(d) : "l"(a), "l"(b))

// ---------------------------------------------------------------------------
// Kernel A: h = selu(X@W1+b1); h2 = h@W2+b2; store h2 + deterministic BN partials
// grid 1024 x 128 threads; 32 rows/block; 4 threads per row (8 outputs each)
// ---------------------------------------------------------------------------
__global__ void __launch_bounds__(128, 8) kernA(
    const float* __restrict__ X,
    const float* __restrict__ W1, const float* __restrict__ b1,
    const float* __restrict__ W2, const float* __restrict__ b2)
{
    extern __shared__ char sm[];
    float* xs  = (float*)sm;                          // 32*68*4 = 8704 B
    float* w1s = (float*)(sm + 8704);                 // 8192 B
    float* w2s = (float*)(sm + 8704 + 8192);          // 4096 B
    float* b1s = (float*)(sm + 8704 + 8192 + 4096);   // 128 B
    float* b2s = b1s + HID;                           // 128 B
    float* hs  = (float*)(sm + 8704 + 8192 + 4096 + 256); // 32*36*4 = 4608 B

    int t = threadIdx.x;
    int rowbase = blockIdx.x * 32;
    const float* Xb = X + (size_t)rowbase * FIN;

    #pragma unroll
    for (int j = 0; j < 4; j++) {
        int idx = t + j * 128;
        float4 v = ((const float4*)Xb)[idx];
        int row = idx >> 4, col = (idx & 15) * 4;
        *(float4*)&xs[row * 68 + col] = v;
    }
    #pragma unroll
    for (int j = 0; j < 4; j++) ((float4*)w1s)[t + j * 128] = ((const float4*)W1)[t + j * 128];
    #pragma unroll
    for (int j = 0; j < 2; j++) ((float4*)w2s)[t + j * 128] = ((const float4*)W2)[t + j * 128];
    if (t < HID) { b1s[t] = b1[t]; b2s[t] = b2[t]; }
    __syncthreads();

    int r  = t >> 2;        // row 0..31
    int j0 = (t & 3) * 8;   // output col group

    u64 acc[4];
    #pragma unroll
    for (int p = 0; p < 4; p++) acc[p] = *(const u64*)&b1s[j0 + 2 * p];
    #pragma unroll 8
    for (int k = 0; k < FIN; k++) {
        float xk = xs[r * 68 + k];
        u64 xv = pk2(xk, xk);
        ulonglong2 w0 = *(const ulonglong2*)&w1s[k * HID + j0];
        ulonglong2 w1v = *(const ulonglong2*)&w1s[k * HID + j0 + 4];
        FFMA2(acc[0], xv, w0.x);
        FFMA2(acc[1], xv, w0.y);
        FFMA2(acc[2], xv, w1v.x);
        FFMA2(acc[3], xv, w1v.y);
    }
    float hv[8];
    #pragma unroll
    for (int p = 0; p < 4; p++) {
        float a, b; upk2(acc[p], a, b);
        hv[2 * p] = selu_f(a); hv[2 * p + 1] = selu_f(b);
    }
    *(float4*)&hs[r * 36 + j0]     = make_float4(hv[0], hv[1], hv[2], hv[3]);
    *(float4*)&hs[r * 36 + j0 + 4] = make_float4(hv[4], hv[5], hv[6], hv[7]);
    __syncthreads();

    u64 acc2[4];
    #pragma unroll
    for (int p = 0; p < 4; p++) acc2[p] = *(const u64*)&b2s[j0 + 2 * p];
    #pragma unroll 8
    for (int k = 0; k < HID; k++) {
        float hk = hs[r * 36 + k];
        u64 hvv = pk2(hk, hk);
        ulonglong2 w0 = *(const ulonglong2*)&w2s[k * HID + j0];
        ulonglong2 w1v = *(const ulonglong2*)&w2s[k * HID + j0 + 4];
        FFMA2(acc2[0], hvv, w0.x);
        FFMA2(acc2[1], hvv, w0.y);
        FFMA2(acc2[2], hvv, w1v.x);
        FFMA2(acc2[3], hvv, w1v.y);
    }
    float o[8];
    #pragma unroll
    for (int p = 0; p < 4; p++) upk2(acc2[p], o[2 * p], o[2 * p + 1]);

    float* H2r = g_h2 + (size_t)(rowbase + r) * HID + j0;
    *(float4*)H2r       = make_float4(o[0], o[1], o[2], o[3]);
    *(float4*)(H2r + 4) = make_float4(o[4], o[5], o[6], o[7]);

    __syncthreads();
    *(float4*)&hs[r * 36 + j0]     = make_float4(o[0], o[1], o[2], o[3]);
    *(float4*)&hs[r * 36 + j0 + 4] = make_float4(o[4], o[5], o[6], o[7]);
    __syncthreads();

    if (t < HID) {
        float s = 0.f, s2 = 0.f;
        #pragma unroll 8
        for (int rr = 0; rr < 32; rr++) {
            float v = hs[rr * 36 + t];
            s += v; s2 += v * v;
        }
        g_part[blockIdx.x][t]       = s;
        g_part[blockIdx.x][HID + t] = s2;
    }
}

// ---------------------------------------------------------------------------
// Kernel B: fold 1024 partials -> scale/shift (deterministic)
// ---------------------------------------------------------------------------
__global__ void kernB(const float* __restrict__ gamma, const float* __restrict__ beta) {
    __shared__ float ps[8][64];
    int t = threadIdx.x;
    int c = t & 31, ch = t >> 5;
    float s = 0.f, s2 = 0.f;
    #pragma unroll 4
    for (int b = ch * 128; b < ch * 128 + 128; b++) {
        s  += g_part[b][c];
        s2 += g_part[b][HID + c];
    }
    ps[ch][c] = s; ps[ch][HID + c] = s2;
    __syncthreads();
    if (t < HID) {
        float S = 0.f, S2 = 0.f;
        #pragma unroll
        for (int ch2 = 0; ch2 < 8; ch2++) { S += ps[ch2][t]; S2 += ps[ch2][HID + t]; }
        float mu  = S  * (1.0f / B_N);
        float var = S2 * (1.0f / B_N) - mu * mu;
        float sc  = gamma[t] * rsqrtf(var + 1e-5f);
        g_scale[t] = sc;
        g_shift[t] = beta[t] - mu * sc;
    }
}

// ---------------------------------------------------------------------------
// Kernel C: e = selu(BN(h2)); D = e @ Wh (+bh in acc init); selu; L1-norm;
// staged transposed epilogue -> coalesced float4 stores.
// grid (12 bands, 64) x 512 threads; NT=8 tiles of 64 rows per block.
// thread = 1 row x 1 head (13 f32x2 acc). head my = t>>6 (warp-uniform),
// row rl = t&63. 2 blocks/SM -> 32 warps/SM.
// smem: bhs[224] | wch[32][224] | sss[64] | epd[32][65] u64 | stg[200][33]
// ---------------------------------------------------------------------------
__global__ void __launch_bounds__(512, 2) kernC(
    const float* __restrict__ Wh, const float* __restrict__ bh,
    float* __restrict__ out)
{
    extern __shared__ char sm[];
    float* bhs = (float*)sm;                               // 896 B
    float* wch = (float*)(sm + 896);                       // 28672 B
    float* sss = (float*)(sm + 896 + 28672);               // 256 B
    u64*   epd = (u64*)(sm + 896 + 28672 + 256);           // 16640 B
    float* stg = (float*)(sm + 896 + 28672 + 256 + 16640); // 200*33*4 = 26400 B

    int t = threadIdx.x;
    int band = blockIdx.x;

    // biases (pad cols -> 0)
    for (int i = t; i < BAND_HG * 28; i += 512) {
        int hgl = i / 28, j = i - hgl * 28;
        bhs[i] = (j < E_N) ? bh[(band * BAND_HG + hgl) * E_N + j] : 0.0f;
    }
    // weights: Wh[hg][k][j] -> wch[k][hgl*28 + j]; zero pad col 25
    for (int i = t; i < BAND_HG * HID * E_N; i += 512) {
        int hgl = i / (HID * E_N);
        int rem = i - hgl * HID * E_N;
        int k = rem / E_N, j = rem - k * E_N;
        wch[k * MB + hgl * 28 + j] = Wh[(size_t)(band * BAND_HG + hgl) * HID * E_N + rem];
    }
    if (t < HID * BAND_HG) {
        int k = t >> 3, hgl = t & 7;
        wch[k * MB + hgl * 28 + 25] = 0.0f;
    }
    if (t < HID) { sss[t] = g_scale[t]; sss[HID + t] = g_shift[t]; }

    int my = t >> 6;        // head within band (warp-uniform)
    int rl = t & 63;        // row within tile
    int tx = rl & 31;       // lane row within 32-row half
    int half_id = rl >> 5;  // which 32-row half this thread's row is in
    int wb = my * 28;
    int r8 = t >> 3;        // epd-fill row (1 float4 per thread)
    int k0 = (t & 7) * 4;   // epd-fill k-group

    int row0 = blockIdx.y * (NT * 64);
    const float* h2p = g_h2 + (size_t)row0 * HID;
    float4 pf = ((const float4*)h2p)[t];

    for (int tile = 0; tile < NT; tile++) {
        __syncthreads();   // weights/sss ready (tile 0) / prev-tile epd+stg reads done
        // epd fill: BN + selu, duplicated f32x2, layout [k][row]
        {
            float vv[4] = {pf.x, pf.y, pf.z, pf.w};
            #pragma unroll
            for (int u = 0; u < 4; u++) {
                float v = fmaf(vv[u], sss[k0 + u], sss[HID + k0 + u]);
                v = selu_f(v);
                epd[(k0 + u) * EPD_STRIDE + r8] = pk2(v, v);
            }
        }
        __syncthreads();

        // prefetch next tile into registers (hidden behind mainloop)
        if (tile < NT - 1) {
            const float* nxt = g_h2 + (size_t)(row0 + 64) * HID;
            pf = ((const float4*)nxt)[t];
        }

        // mainloop; acc init = bias
        u64 acc[13];
        #pragma unroll
        for (int p = 0; p < 13; p++) acc[p] = *(const u64*)&bhs[wb + 2 * p];
        #pragma unroll 4
        for (int k = 0; k < HID; k++) {
            u64 e0 = epd[k * EPD_STRIDE + rl];
            const float* wr = &wch[k * MB + wb];
            ulonglong2 wA = *(const ulonglong2*)(wr);
            ulonglong2 wB = *(const ulonglong2*)(wr + 4);
            ulonglong2 wC = *(const ulonglong2*)(wr + 8);
            ulonglong2 wD = *(const ulonglong2*)(wr + 12);
            ulonglong2 wE = *(const ulonglong2*)(wr + 16);
            ulonglong2 wF = *(const ulonglong2*)(wr + 20);
            u64 wG = *(const u64*)(wr + 24);
            FFMA2(acc[0], e0, wA.x);
            FFMA2(acc[1], e0, wA.y);
            FFMA2(acc[2], e0, wB.x);
            FFMA2(acc[3], e0, wB.y);
            FFMA2(acc[4], e0, wC.x);
            FFMA2(acc[5], e0, wC.y);
            FFMA2(acc[6], e0, wD.x);
            FFMA2(acc[7], e0, wD.y);
            FFMA2(acc[8], e0, wE.x);
            FFMA2(acc[9], e0, wE.y);
            FFMA2(acc[10], e0, wF.x);
            FFMA2(acc[11], e0, wF.y);
            FFMA2(acc[12], e0, wG);
        }

        // epilogue: two 32-row halves; half ri staged by threads with half_id==ri
        #pragma unroll
        for (int ri = 0; ri < 2; ri++) {
            if (ri) __syncthreads();   // store-loop reads of stg done
            if (half_id == ri) {
                float v[26];
                #pragma unroll
                for (int p = 0; p < 13; p++) upk2(acc[p], v[2 * p], v[2 * p + 1]);
                float s = 0.f;
                #pragma unroll
                for (int j = 0; j < E_N; j++) {
                    float d = selu_f(v[j]);
                    v[j] = d;
                    s += fabsf(d);
                }
                float inv = __fdividef(1.0f, fmaxf(s, 1e-12f));
                #pragma unroll
                for (int j = 0; j < E_N; j++)
                    stg[(my * E_N + j) * 33 + tx] = v[j] * inv;  // sign(d)*|d|/l1 == d/l1
            }
            __syncthreads();
            // write 32 rows x 200 cols, coalesced STG.128 (all 512 threads)
            float* ob = out + (size_t)(row0 + 32 * ri) * (HG * E_N) + band * (BAND_HG * E_N);
            for (int i = t; i < 32 * 50; i += 512) {
                int r = i / 50, q = i - r * 50;
                float4 vv;
                vv.x = stg[(4 * q + 0) * 33 + r];
                vv.y = stg[(4 * q + 1) * 33 + r];
                vv.z = stg[(4 * q + 2) * 33 + r];
                vv.w = stg[(4 * q + 3) * 33 + r];
                *(float4*)(ob + (size_t)r * (HG * E_N) + 4 * q) = vv;  // 16B aligned
            }
        }
        row0 += 64;
    }
}

// ---------------------------------------------------------------------------
extern "C" void kernel_launch(void* const* d_in, const int* in_sizes, int n_in,
                              void* d_out, int out_size) {
    const float* X     = (const float*)d_in[0];
    const float* W1    = (const float*)d_in[1];
    const float* b1    = (const float*)d_in[2];
    const float* W2    = (const float*)d_in[3];
    const float* b2    = (const float*)d_in[4];
    const float* gamma = (const float*)d_in[5];
    const float* beta  = (const float*)d_in[6];
    const float* Wh    = (const float*)d_in[7];
    const float* bh    = (const float*)d_in[8];
    float* out = (float*)d_out;

    cudaFuncSetAttribute(kernA, cudaFuncAttributeMaxDynamicSharedMemorySize, 25856);
    cudaFuncSetAttribute(kernC, cudaFuncAttributeMaxDynamicSharedMemorySize, 72864);

    kernA<<<1024, 128, 25856>>>(X, W1, b1, W2, b2);
    kernB<<<1, 256>>>(gamma, beta);
    kernC<<<dim3(NBAND, 64), 512, 72864>>>(Wh, bh, out);
}

// round 7
// speedup vs baseline: 1.2813x; 1.2813x over previous
#include <cuda_runtime.h>

#define B_N   32768
#define FIN   64
#define HID   32
#define E_N   25
#define HG    96
#define BAND_HG 8
#define NBAND 12
#define MB    224      // 8 heads * 28 (16B-aligned head base)
#define EPD_STRIDE 65  // u64 row stride for e-tile
#define NT    8        // row-tiles per kernC block

typedef unsigned long long u64;

// scratch (static device globals — no allocation)
__device__ float g_h2[B_N * HID];          // 4 MB intermediate
__device__ float g_part[1024][2 * HID];    // per-block BN partial sums
__device__ float g_scale[HID];
__device__ float g_shift[HID];

__device__ __forceinline__ float selu_f(float x) {
    float p = 1.0507009873554805f * x;
    float n = 1.7580993408473766f * (__expf(x) - 1.0f);  // lambda*alpha
    return x > 0.0f ? p : n;
}
__device__ __forceinline__ u64 pk2(float lo, float hi) {
    u64 r;
    asm("mov.b64 %0, {%1,%2};" : "=l"(r)
        : "r"(__float_as_uint(lo)), "r"(__float_as_uint(hi)));
    return r;
}
__device__ __forceinline__ void upk2(u64 v, float& lo, float& hi) {
    unsigned int a, b;
    asm("mov.b64 {%0,%1}, %2;" : "=r"(a), "=r"(b) : "l"(v));
    lo = __uint_as_float(a); hi = __uint_as_float(b);
}
// packed fp32x2 FMA (FFMA2) — only reachable via PTX
#define FFMA2(d, a, b) asm("fma.rn.f32x2 %0, %1, %2, %0;" : "+l"(d) : "l"(a), "l"(b))

// staging address: [m][r] pitch 32 with XOR swizzle -> conflict-free both ways
__device__ __forceinline__ int stg_addr(int m, int r) {
    return m * 32 + (r ^ ((m >> 2) & 31));
}

// ---------------------------------------------------------------------------
// Kernel A: h = selu(X@W1+b1); h2 = h@W2+b2; store h2 + deterministic BN partials
// grid 1024 x 128 threads; 32 rows/block; 4 threads per row (8 outputs each)
// ---------------------------------------------------------------------------
__global__ void __launch_bounds__(128, 8) kernA(
    const float* __restrict__ X,
    const float* __restrict__ W1, const float* __restrict__ b1,
    const float* __restrict__ W2, const float* __restrict__ b2)
{
    extern __shared__ char sm[];
    float* xs  = (float*)sm;                          // 32*68*4 = 8704 B
    float* w1s = (float*)(sm + 8704);                 // 8192 B
    float* w2s = (float*)(sm + 8704 + 8192);          // 4096 B
    float* b1s = (float*)(sm + 8704 + 8192 + 4096);   // 128 B
    float* b2s = b1s + HID;                           // 128 B
    float* hs  = (float*)(sm + 8704 + 8192 + 4096 + 256); // 32*36*4 = 4608 B

    int t = threadIdx.x;
    int rowbase = blockIdx.x * 32;
    const float* Xb = X + (size_t)rowbase * FIN;

    #pragma unroll
    for (int j = 0; j < 4; j++) {
        int idx = t + j * 128;
        float4 v = ((const float4*)Xb)[idx];
        int row = idx >> 4, col = (idx & 15) * 4;
        *(float4*)&xs[row * 68 + col] = v;
    }
    #pragma unroll
    for (int j = 0; j < 4; j++) ((float4*)w1s)[t + j * 128] = ((const float4*)W1)[t + j * 128];
    #pragma unroll
    for (int j = 0; j < 2; j++) ((float4*)w2s)[t + j * 128] = ((const float4*)W2)[t + j * 128];
    if (t < HID) { b1s[t] = b1[t]; b2s[t] = b2[t]; }
    __syncthreads();

    int r  = t >> 2;        // row 0..31
    int j0 = (t & 3) * 8;   // output col group

    u64 acc[4];
    #pragma unroll
    for (int p = 0; p < 4; p++) acc[p] = *(const u64*)&b1s[j0 + 2 * p];
    #pragma unroll 8
    for (int k = 0; k < FIN; k++) {
        float xk = xs[r * 68 + k];
        u64 xv = pk2(xk, xk);
        ulonglong2 w0 = *(const ulonglong2*)&w1s[k * HID + j0];
        ulonglong2 w1v = *(const ulonglong2*)&w1s[k * HID + j0 + 4];
        FFMA2(acc[0], xv, w0.x);
        FFMA2(acc[1], xv, w0.y);
        FFMA2(acc[2], xv, w1v.x);
        FFMA2(acc[3], xv, w1v.y);
    }
    float hv[8];
    #pragma unroll
    for (int p = 0; p < 4; p++) {
        float a, b; upk2(acc[p], a, b);
        hv[2 * p] = selu_f(a); hv[2 * p + 1] = selu_f(b);
    }
    *(float4*)&hs[r * 36 + j0]     = make_float4(hv[0], hv[1], hv[2], hv[3]);
    *(float4*)&hs[r * 36 + j0 + 4] = make_float4(hv[4], hv[5], hv[6], hv[7]);
    __syncthreads();

    u64 acc2[4];
    #pragma unroll
    for (int p = 0; p < 4; p++) acc2[p] = *(const u64*)&b2s[j0 + 2 * p];
    #pragma unroll 8
    for (int k = 0; k < HID; k++) {
        float hk = hs[r * 36 + k];
        u64 hvv = pk2(hk, hk);
        ulonglong2 w0 = *(const ulonglong2*)&w2s[k * HID + j0];
        ulonglong2 w1v = *(const ulonglong2*)&w2s[k * HID + j0 + 4];
        FFMA2(acc2[0], hvv, w0.x);
        FFMA2(acc2[1], hvv, w0.y);
        FFMA2(acc2[2], hvv, w1v.x);
        FFMA2(acc2[3], hvv, w1v.y);
    }
    float o[8];
    #pragma unroll
    for (int p = 0; p < 4; p++) upk2(acc2[p], o[2 * p], o[2 * p + 1]);

    float* H2r = g_h2 + (size_t)(rowbase + r) * HID + j0;
    *(float4*)H2r       = make_float4(o[0], o[1], o[2], o[3]);
    *(float4*)(H2r + 4) = make_float4(o[4], o[5], o[6], o[7]);

    __syncthreads();
    *(float4*)&hs[r * 36 + j0]     = make_float4(o[0], o[1], o[2], o[3]);
    *(float4*)&hs[r * 36 + j0 + 4] = make_float4(o[4], o[5], o[6], o[7]);
    __syncthreads();

    if (t < HID) {
        float s = 0.f, s2 = 0.f;
        #pragma unroll 8
        for (int rr = 0; rr < 32; rr++) {
            float v = hs[rr * 36 + t];
            s += v; s2 += v * v;
        }
        g_part[blockIdx.x][t]       = s;
        g_part[blockIdx.x][HID + t] = s2;
    }
}

// ---------------------------------------------------------------------------
// Kernel B: fold 1024 partials -> scale/shift (deterministic)
// ---------------------------------------------------------------------------
__global__ void kernB(const float* __restrict__ gamma, const float* __restrict__ beta) {
    __shared__ float ps[8][64];
    int t = threadIdx.x;
    int c = t & 31, ch = t >> 5;
    float s = 0.f, s2 = 0.f;
    #pragma unroll 4
    for (int b = ch * 128; b < ch * 128 + 128; b++) {
        s  += g_part[b][c];
        s2 += g_part[b][HID + c];
    }
    ps[ch][c] = s; ps[ch][HID + c] = s2;
    __syncthreads();
    if (t < HID) {
        float S = 0.f, S2 = 0.f;
        #pragma unroll
        for (int ch2 = 0; ch2 < 8; ch2++) { S += ps[ch2][t]; S2 += ps[ch2][HID + t]; }
        float mu  = S  * (1.0f / B_N);
        float var = S2 * (1.0f / B_N) - mu * mu;
        float sc  = gamma[t] * rsqrtf(var + 1e-5f);
        g_scale[t] = sc;
        g_shift[t] = beta[t] - mu * sc;
    }
}

// ---------------------------------------------------------------------------
// Kernel C: e = selu(BN(h2)); D = e @ Wh (+bh in acc init); selu; L1-norm;
// swizzled staged transposed epilogue -> conflict-free LDS + coalesced STG.128.
// grid (12 bands, 64) x 256 threads; NT=8 tiles of 64 rows per block.
// thread: 2 rows x 13 m-pairs (one head) -> 26 f32x2 accumulators
// smem: bhs[224] | wch[32][224] | sss[64] | epd[32][65] u64 | stg[200*32] swizzled
// ---------------------------------------------------------------------------
__global__ void __launch_bounds__(256, 2) kernC(
    const float* __restrict__ Wh, const float* __restrict__ bh,
    float* __restrict__ out)
{
    extern __shared__ char sm[];
    float* bhs = (float*)sm;                               // 896 B
    float* wch = (float*)(sm + 896);                       // 28672 B
    float* sss = (float*)(sm + 896 + 28672);               // 256 B
    u64*   epd = (u64*)(sm + 896 + 28672 + 256);           // 16640 B
    float* stg = (float*)(sm + 896 + 28672 + 256 + 16640); // 200*32*4 = 25600 B

    int t = threadIdx.x;
    int band = blockIdx.x;

    // biases (pad cols -> 0)
    for (int i = t; i < BAND_HG * 28; i += 256) {
        int hgl = i / 28, j = i - hgl * 28;
        bhs[i] = (j < E_N) ? bh[(band * BAND_HG + hgl) * E_N + j] : 0.0f;
    }
    // weights: Wh[hg][k][j] -> wch[k][hgl*28 + j]; zero pad col 25
    for (int i = t; i < BAND_HG * HID * E_N; i += 256) {
        int hgl = i / (HID * E_N);
        int rem = i - hgl * HID * E_N;
        int k = rem / E_N, j = rem - k * E_N;
        wch[k * MB + hgl * 28 + j] = Wh[(size_t)(band * BAND_HG + hgl) * HID * E_N + rem];
    }
    if (t < HID * BAND_HG) {
        int k = t >> 3, hgl = t & 7;
        wch[k * MB + hgl * 28 + 25] = 0.0f;
    }
    if (t < HID) { sss[t] = g_scale[t]; sss[HID + t] = g_shift[t]; }

    int tx = t & 31;        // row lane
    int my = t >> 5;        // head within band (warp-uniform) == warp id
    int wb = my * 28;
    int r8 = t >> 2;        // epd-fill row
    int k0 = (t & 3) * 8;   // epd-fill k-group

    int row0 = blockIdx.y * (NT * 64);
    const float* h2p = g_h2 + (size_t)row0 * HID;
    float4 pf0 = ((const float4*)h2p)[t * 2];
    float4 pf1 = ((const float4*)h2p)[t * 2 + 1];

    for (int tile = 0; tile < NT; tile++) {
        __syncthreads();   // weights/sss ready (tile 0) / prev-tile epd+stg reads done
        // epd fill: BN + selu, duplicated f32x2, layout [k][row]
        {
            float vv[8] = {pf0.x, pf0.y, pf0.z, pf0.w, pf1.x, pf1.y, pf1.z, pf1.w};
            #pragma unroll
            for (int u = 0; u < 8; u++) {
                float v = fmaf(vv[u], sss[k0 + u], sss[HID + k0 + u]);
                v = selu_f(v);
                epd[(k0 + u) * EPD_STRIDE + r8] = pk2(v, v);
            }
        }
        __syncthreads();

        // prefetch next tile into registers (hidden behind mainloop)
        if (tile < NT - 1) {
            const float* nxt = g_h2 + (size_t)(row0 + 64) * HID;
            pf0 = ((const float4*)nxt)[t * 2];
            pf1 = ((const float4*)nxt)[t * 2 + 1];
        }

        // mainloop; acc init = bias
        u64 acc[2][13];
        #pragma unroll
        for (int p = 0; p < 13; p++) {
            u64 bp = *(const u64*)&bhs[wb + 2 * p];
            acc[0][p] = bp; acc[1][p] = bp;
        }
        #pragma unroll 4
        for (int k = 0; k < HID; k++) {
            u64 e0 = epd[k * EPD_STRIDE + tx];
            u64 e1 = epd[k * EPD_STRIDE + tx + 32];
            const float* wr = &wch[k * MB + wb];
            ulonglong2 wA = *(const ulonglong2*)(wr);
            ulonglong2 wB = *(const ulonglong2*)(wr + 4);
            ulonglong2 wC = *(const ulonglong2*)(wr + 8);
            ulonglong2 wD = *(const ulonglong2*)(wr + 12);
            ulonglong2 wE = *(const ulonglong2*)(wr + 16);
            ulonglong2 wF = *(const ulonglong2*)(wr + 20);
            u64 wG = *(const u64*)(wr + 24);
            FFMA2(acc[0][0], e0, wA.x);  FFMA2(acc[1][0], e1, wA.x);
            FFMA2(acc[0][1], e0, wA.y);  FFMA2(acc[1][1], e1, wA.y);
            FFMA2(acc[0][2], e0, wB.x);  FFMA2(acc[1][2], e1, wB.x);
            FFMA2(acc[0][3], e0, wB.y);  FFMA2(acc[1][3], e1, wB.y);
            FFMA2(acc[0][4], e0, wC.x);  FFMA2(acc[1][4], e1, wC.x);
            FFMA2(acc[0][5], e0, wC.y);  FFMA2(acc[1][5], e1, wC.y);
            FFMA2(acc[0][6], e0, wD.x);  FFMA2(acc[1][6], e1, wD.x);
            FFMA2(acc[0][7], e0, wD.y);  FFMA2(acc[1][7], e1, wD.y);
            FFMA2(acc[0][8], e0, wE.x);  FFMA2(acc[1][8], e1, wE.x);
            FFMA2(acc[0][9], e0, wE.y);  FFMA2(acc[1][9], e1, wE.y);
            FFMA2(acc[0][10], e0, wF.x); FFMA2(acc[1][10], e1, wF.x);
            FFMA2(acc[0][11], e0, wF.y); FFMA2(acc[1][11], e1, wF.y);
            FFMA2(acc[0][12], e0, wG);   FFMA2(acc[1][12], e1, wG);
        }

        // epilogue: two 32-row halves; swizzled staging, conflict-free both ways
        #pragma unroll
        for (int ri = 0; ri < 2; ri++) {
            if (ri) __syncthreads();   // store-loop reads of stg done
            {
                float v[26];
                #pragma unroll
                for (int p = 0; p < 13; p++) upk2(acc[ri][p], v[2 * p], v[2 * p + 1]);
                float s = 0.f;
                #pragma unroll
                for (int j = 0; j < E_N; j++) {
                    float d = selu_f(v[j]);
                    v[j] = d;
                    s += fabsf(d);
                }
                float inv = __fdividef(1.0f, fmaxf(s, 1e-12f));
                #pragma unroll
                for (int j = 0; j < E_N; j++)
                    stg[stg_addr(my * E_N + j, tx)] = v[j] * inv;  // sign(d)*|d|/l1 == d/l1
            }
            __syncthreads();
            // write 32 rows x 200 cols: warp my handles rows {my, my+8, my+16, my+24},
            // lanes span q -> conflict-free LDS (bank = rr ^ q) + contiguous STG.128
            float* ob = out + (size_t)(row0 + 32 * ri) * (HG * E_N) + band * (BAND_HG * E_N);
            #pragma unroll
            for (int rr = my; rr < 32; rr += 8) {
                float* orow = ob + (size_t)rr * (HG * E_N);
                #pragma unroll
                for (int qq = 0; qq < 2; qq++) {
                    int q = tx + qq * 32;
                    if (q < 50) {
                        int m = 4 * q;
                        float4 vv;
                        vv.x = stg[stg_addr(m + 0, rr)];
                        vv.y = stg[stg_addr(m + 1, rr)];
                        vv.z = stg[stg_addr(m + 2, rr)];
                        vv.w = stg[stg_addr(m + 3, rr)];
                        *(float4*)(orow + 4 * q) = vv;  // 16B aligned
                    }
                }
            }
        }
        row0 += 64;
    }
}

// ---------------------------------------------------------------------------
extern "C" void kernel_launch(void* const* d_in, const int* in_sizes, int n_in,
                              void* d_out, int out_size) {
    const float* X     = (const float*)d_in[0];
    const float* W1    = (const float*)d_in[1];
    const float* b1    = (const float*)d_in[2];
    const float* W2    = (const float*)d_in[3];
    const float* b2    = (const float*)d_in[4];
    const float* gamma = (const float*)d_in[5];
    const float* beta  = (const float*)d_in[6];
    const float* Wh    = (const float*)d_in[7];
    const float* bh    = (const float*)d_in[8];
    float* out = (float*)d_out;

    cudaFuncSetAttribute(kernA, cudaFuncAttributeMaxDynamicSharedMemorySize, 25856);
    cudaFuncSetAttribute(kernC, cudaFuncAttributeMaxDynamicSharedMemorySize, 72064);

    kernA<<<1024, 128, 25856>>>(X, W1, b1, W2, b2);
    kernB<<<1, 256>>>(gamma, beta);
    kernC<<<dim3(NBAND, 64), 256, 72064>>>(Wh, bh, out);
}

// round 10
// speedup vs baseline: 1.7251x; 1.3464x over previous
#include <cuda_runtime.h>
#include <cuda_bf16.h>
#include <cstdint>

#define B_N   32768
#define FIN   64
#define HID   32
#define E_N   25
#define HG    96
#define NBAND 12

typedef unsigned long long u64;
typedef unsigned int u32;

// scratch (static device globals — no allocation)
__device__ float g_h2[B_N * HID];            // 4 MB
__device__ float g_part[1024][2 * HID];
__device__ float g_scale[HID];
__device__ float g_shift[HID];
__device__ u32   g_esplit[B_N * 32];         // 4 MB: per row 128B = bf16[64]: hi k0..31 | lo k0..31
__device__ u32   g_wsplit[NBAND * 256 * 32]; // 384 KB: per band 256 B-rows x 128B (same hi|lo layout)

__device__ __forceinline__ float selu_f(float x) {
    float p = 1.0507009873554805f * x;
    float n = 1.7580993408473766f * (__expf(x) - 1.0f);
    return x > 0.0f ? p : n;
}
__device__ __forceinline__ u64 pk2(float lo, float hi) {
    u64 r;
    asm("mov.b64 %0, {%1,%2};" : "=l"(r)
        : "r"(__float_as_uint(lo)), "r"(__float_as_uint(hi)));
    return r;
}
__device__ __forceinline__ void upk2(u64 v, float& lo, float& hi) {
    u32 a, b;
    asm("mov.b64 {%0,%1}, %2;" : "=r"(a), "=r"(b) : "l"(v));
    lo = __uint_as_float(a); hi = __uint_as_float(b);
}
#define FFMA2(d, a, b) asm("fma.rn.f32x2 %0, %1, %2, %0;" : "+l"(d) : "l"(a), "l"(b))

__device__ __forceinline__ uint16_t bf16b(float x) {
    __nv_bfloat16 h = __float2bfloat16(x);
    return *(uint16_t*)&h;
}
__device__ __forceinline__ float bf16f(uint16_t b) {
    __nv_bfloat16 h = *(__nv_bfloat16*)&b;
    return (float)h;
}

// warp-level bf16 MMA (HMMA), sm_80+ baseline — compiles for compute_103
__device__ __forceinline__ void mma16816(float* c, const u32* a, u32 b0, u32 b1) {
    asm volatile(
        "mma.sync.aligned.m16n8k16.row.col.f32.bf16.bf16.f32 "
        "{%0,%1,%2,%3}, {%4,%5,%6,%7}, {%8,%9}, {%0,%1,%2,%3};"
        : "+f"(c[0]), "+f"(c[1]), "+f"(c[2]), "+f"(c[3])
        : "r"(a[0]), "r"(a[1]), "r"(a[2]), "r"(a[3]), "r"(b0), "r"(b1));
}

// ---------------------------------------------------------------------------
// Kernel A: h = selu(X@W1+b1); h2 = h@W2+b2; store h2 + BN partials
// ---------------------------------------------------------------------------
__global__ void __launch_bounds__(128, 8) kernA(
    const float* __restrict__ X,
    const float* __restrict__ W1, const float* __restrict__ b1,
    const float* __restrict__ W2, const float* __restrict__ b2)
{
    extern __shared__ char sm[];
    float* xs  = (float*)sm;
    float* w1s = (float*)(sm + 8704);
    float* w2s = (float*)(sm + 8704 + 8192);
    float* b1s = (float*)(sm + 8704 + 8192 + 4096);
    float* b2s = b1s + HID;
    float* hs  = (float*)(sm + 8704 + 8192 + 4096 + 256);

    int t = threadIdx.x;
    int rowbase = blockIdx.x * 32;
    const float* Xb = X + (size_t)rowbase * FIN;

    #pragma unroll
    for (int j = 0; j < 4; j++) {
        int idx = t + j * 128;
        float4 v = ((const float4*)Xb)[idx];
        int row = idx >> 4, col = (idx & 15) * 4;
        *(float4*)&xs[row * 68 + col] = v;
    }
    #pragma unroll
    for (int j = 0; j < 4; j++) ((float4*)w1s)[t + j * 128] = ((const float4*)W1)[t + j * 128];
    #pragma unroll
    for (int j = 0; j < 2; j++) ((float4*)w2s)[t + j * 128] = ((const float4*)W2)[t + j * 128];
    if (t < HID) { b1s[t] = b1[t]; b2s[t] = b2[t]; }
    __syncthreads();

    int r  = t >> 2;
    int j0 = (t & 3) * 8;

    u64 acc[4];
    #pragma unroll
    for (int p = 0; p < 4; p++) acc[p] = *(const u64*)&b1s[j0 + 2 * p];
    #pragma unroll 8
    for (int k = 0; k < FIN; k++) {
        float xk = xs[r * 68 + k];
        u64 xv = pk2(xk, xk);
        ulonglong2 w0 = *(const ulonglong2*)&w1s[k * HID + j0];
        ulonglong2 w1v = *(const ulonglong2*)&w1s[k * HID + j0 + 4];
        FFMA2(acc[0], xv, w0.x);
        FFMA2(acc[1], xv, w0.y);
        FFMA2(acc[2], xv, w1v.x);
        FFMA2(acc[3], xv, w1v.y);
    }
    float hv[8];
    #pragma unroll
    for (int p = 0; p < 4; p++) {
        float a, b; upk2(acc[p], a, b);
        hv[2 * p] = selu_f(a); hv[2 * p + 1] = selu_f(b);
    }
    *(float4*)&hs[r * 36 + j0]     = make_float4(hv[0], hv[1], hv[2], hv[3]);
    *(float4*)&hs[r * 36 + j0 + 4] = make_float4(hv[4], hv[5], hv[6], hv[7]);
    __syncthreads();

    u64 acc2[4];
    #pragma unroll
    for (int p = 0; p < 4; p++) acc2[p] = *(const u64*)&b2s[j0 + 2 * p];
    #pragma unroll 8
    for (int k = 0; k < HID; k++) {
        float hk = hs[r * 36 + k];
        u64 hvv = pk2(hk, hk);
        ulonglong2 w0 = *(const ulonglong2*)&w2s[k * HID + j0];
        ulonglong2 w1v = *(const ulonglong2*)&w2s[k * HID + j0 + 4];
        FFMA2(acc2[0], hvv, w0.x);
        FFMA2(acc2[1], hvv, w0.y);
        FFMA2(acc2[2], hvv, w1v.x);
        FFMA2(acc2[3], hvv, w1v.y);
    }
    float o[8];
    #pragma unroll
    for (int p = 0; p < 4; p++) upk2(acc2[p], o[2 * p], o[2 * p + 1]);

    float* H2r = g_h2 + (size_t)(rowbase + r) * HID + j0;
    *(float4*)H2r       = make_float4(o[0], o[1], o[2], o[3]);
    *(float4*)(H2r + 4) = make_float4(o[4], o[5], o[6], o[7]);

    __syncthreads();
    *(float4*)&hs[r * 36 + j0]     = make_float4(o[0], o[1], o[2], o[3]);
    *(float4*)&hs[r * 36 + j0 + 4] = make_float4(o[4], o[5], o[6], o[7]);
    __syncthreads();

    if (t < HID) {
        float s = 0.f, s2 = 0.f;
        #pragma unroll 8
        for (int rr = 0; rr < 32; rr++) {
            float v = hs[rr * 36 + t];
            s += v; s2 += v * v;
        }
        g_part[blockIdx.x][t]       = s;
        g_part[blockIdx.x][HID + t] = s2;
    }
}

// ---------------------------------------------------------------------------
// Kernel B: fold partials -> scale/shift
// ---------------------------------------------------------------------------
__global__ void kernB(const float* __restrict__ gamma, const float* __restrict__ beta) {
    __shared__ float ps[8][64];
    int t = threadIdx.x;
    int c = t & 31, ch = t >> 5;
    float s = 0.f, s2 = 0.f;
    #pragma unroll 4
    for (int b = ch * 128; b < ch * 128 + 128; b++) {
        s  += g_part[b][c];
        s2 += g_part[b][HID + c];
    }
    ps[ch][c] = s; ps[ch][HID + c] = s2;
    __syncthreads();
    if (t < HID) {
        float S = 0.f, S2 = 0.f;
        #pragma unroll
        for (int ch2 = 0; ch2 < 8; ch2++) { S += ps[ch2][t]; S2 += ps[ch2][HID + t]; }
        float mu  = S  * (1.0f / B_N);
        float var = S2 * (1.0f / B_N) - mu * mu;
        float sc  = gamma[t] * rsqrtf(var + 1e-5f);
        g_scale[t] = sc;
        g_shift[t] = beta[t] - mu * sc;
    }
}

// ---------------------------------------------------------------------------
// Kernel E: e = selu(BN(h2)) -> bf16 hi/lo split -> g_esplit
// ---------------------------------------------------------------------------
__global__ void __launch_bounds__(128) kernE() {
    int row = blockIdx.x * 128 + threadIdx.x;
    const float4* hp = (const float4*)(g_h2 + (size_t)row * HID);
    u32 w[32];
    #pragma unroll
    for (int q = 0; q < 8; q++) {
        float4 v = hp[q];
        float e0 = selu_f(fmaf(v.x, g_scale[4 * q + 0], g_shift[4 * q + 0]));
        float e1 = selu_f(fmaf(v.y, g_scale[4 * q + 1], g_shift[4 * q + 1]));
        float e2 = selu_f(fmaf(v.z, g_scale[4 * q + 2], g_shift[4 * q + 2]));
        float e3 = selu_f(fmaf(v.w, g_scale[4 * q + 3], g_shift[4 * q + 3]));
        uint16_t h0 = bf16b(e0), h1 = bf16b(e1), h2v = bf16b(e2), h3 = bf16b(e3);
        w[2 * q]      = (u32)h0 | ((u32)h1 << 16);
        w[2 * q + 1]  = (u32)h2v | ((u32)h3 << 16);
        uint16_t l0 = bf16b(e0 - bf16f(h0)), l1 = bf16b(e1 - bf16f(h1));
        uint16_t l2 = bf16b(e2 - bf16f(h2v)), l3 = bf16b(e3 - bf16f(h3));
        w[16 + 2 * q]     = (u32)l0 | ((u32)l1 << 16);
        w[16 + 2 * q + 1] = (u32)l2 | ((u32)l3 << 16);
    }
    uint4* op = (uint4*)g_esplit + (size_t)row * 8;
    #pragma unroll
    for (int q = 0; q < 8; q++)
        op[q] = make_uint4(w[4 * q], w[4 * q + 1], w[4 * q + 2], w[4 * q + 3]);
}

// ---------------------------------------------------------------------------
// Kernel W: weight bf16 hi/lo split -> g_wsplit  (B-row = hgl*32 + j, j>=25 zero)
// ---------------------------------------------------------------------------
__global__ void __launch_bounds__(256) kernW(const float* __restrict__ Wh) {
    int band = blockIdx.x;
    int t = threadIdx.x;
    int hgl = t >> 5, j = t & 31;
    u32 w[32];
    #pragma unroll
    for (int i = 0; i < 32; i++) w[i] = 0u;
    if (j < E_N) {
        const float* src = Wh + ((size_t)(band * 8 + hgl) * HID) * E_N + j;
        #pragma unroll
        for (int ww = 0; ww < 16; ww++) {
            float v0 = src[(2 * ww) * E_N];
            float v1 = src[(2 * ww + 1) * E_N];
            uint16_t h0 = bf16b(v0), h1 = bf16b(v1);
            w[ww] = (u32)h0 | ((u32)h1 << 16);
            uint16_t l0 = bf16b(v0 - bf16f(h0)), l1 = bf16b(v1 - bf16f(h1));
            w[16 + ww] = (u32)l0 | ((u32)l1 << 16);
        }
    }
    uint4* dst = (uint4*)g_wsplit + ((size_t)band * 256 + t) * 8;
    #pragma unroll
    for (int q = 0; q < 8; q++)
        dst[q] = make_uint4(w[4 * q], w[4 * q + 1], w[4 * q + 2], w[4 * q + 3]);
}

// ---------------------------------------------------------------------------
// Kernel C: D[128 x 64] = e-split[128 x 64k] x w-split[64n x 64k] via
// mma.sync m16n8k16 bf16 (3 products: hi*hi + hi*lo + lo*hi), then
// bias + SELU + PER-HEAD L1-normalize + compacted staging -> coalesced stores.
// grid (48 head-pairs, 256 row-blocks) x 256 threads (8 warps).
// warp w: m-tile rows [16w,16w+16); 8 n-tiles of 8 cols (n-tiles 0-3 = head0,
// 4-7 = head1 — L1 sums kept separate per head).
// ---------------------------------------------------------------------------
__global__ void __launch_bounds__(256) kernC(const float* __restrict__ bh,
                                             float* __restrict__ out)
{
    extern __shared__ char sm[];
    u32* As32 = (u32*)sm;               // row stride 36 u32
    u32* Bs32 = (u32*)(sm + 18432);     // row stride 36 u32
    float* stg = (float*)sm;            // [128][67], alias (post-MMA)
    float* bhs = (float*)(sm + 34336);  // [64]

    int t = threadIdx.x;
    int wid = t >> 5, lane = t & 31;
    int g = lane >> 2, tq = lane & 3;
    int hpg = blockIdx.x;
    int band = hpg >> 2, hp = hpg & 3;
    int row0 = blockIdx.y * 128;

    // A fill: 128 rows x 8 uint4, padded to 144B rows
    {
        const uint4* srcA = (const uint4*)g_esplit + (size_t)row0 * 8;
        #pragma unroll
        for (int i = t; i < 1024; i += 256) {
            int r = i >> 3, j = i & 7;
            *(uint4*)(sm + r * 144 + j * 16) = srcA[i];
        }
    }
    // B fill: 64 rows x 8 uint4
    {
        const uint4* srcB = (const uint4*)g_wsplit + ((size_t)band * 256 + hp * 64) * 8;
        #pragma unroll
        for (int i = t; i < 512; i += 256) {
            int r = i >> 3, j = i & 7;
            *(uint4*)(sm + 18432 + r * 144 + j * 16) = srcB[i];
        }
    }
    if (t < 64) {
        int hh = t >> 5, j = t & 31;
        int head = band * 8 + hp * 2 + hh;
        bhs[t] = (j < E_N) ? bh[head * E_N + j] : 0.0f;
    }
    __syncthreads();

    // A fragments: 4 k-blocks of 16 (kb 0,1 = hi; 2,3 = lo)
    int m0 = wid * 16;
    u32 aa[4][4];
    #pragma unroll
    for (int kb = 0; kb < 4; kb++) {
        int base = kb * 8 + tq;
        aa[kb][0] = As32[(m0 + g) * 36 + base];
        aa[kb][1] = As32[(m0 + g + 8) * 36 + base];
        aa[kb][2] = As32[(m0 + g) * 36 + base + 4];
        aa[kb][3] = As32[(m0 + g + 8) * 36 + base + 4];
    }

    float c[8][4];
    #pragma unroll
    for (int nt = 0; nt < 8; nt++)
        #pragma unroll
        for (int q = 0; q < 4; q++) c[nt][q] = 0.0f;

    #pragma unroll
    for (int nt = 0; nt < 8; nt++) {
        int nb = (nt * 8 + g) * 36 + tq;
        u32 b00 = Bs32[nb],          b01 = Bs32[nb + 4];        // B hi kb0
        u32 b10 = Bs32[nb + 8],      b11 = Bs32[nb + 12];       // B hi kb1
        u32 b20 = Bs32[nb + 16],     b21 = Bs32[nb + 20];       // B lo kb2
        u32 b30 = Bs32[nb + 24],     b31 = Bs32[nb + 28];       // B lo kb3
        mma16816(c[nt], aa[0], b00, b01);   // hi*hi
        mma16816(c[nt], aa[1], b10, b11);
        mma16816(c[nt], aa[0], b20, b21);   // hi*lo
        mma16816(c[nt], aa[1], b30, b31);
        mma16816(c[nt], aa[2], b00, b01);   // lo*hi
        mma16816(c[nt], aa[3], b10, b11);
    }
    __syncthreads();   // all MMA smem reads done -> stg may overwrite A/B

    // epilogue: bias + selu; PER-HEAD abs row sums (head0 = nt 0..3, head1 = nt 4..7)
    float xr[8][4];
    float s0g = 0.f, s0h = 0.f;   // head0: row g, row g+8
    float s1g = 0.f, s1h = 0.f;   // head1: row g, row g+8
    #pragma unroll
    for (int nt = 0; nt < 8; nt++) {
        float b0v = bhs[nt * 8 + 2 * tq];
        float b1v = bhs[nt * 8 + 2 * tq + 1];
        float x0 = selu_f(c[nt][0] + b0v);
        float x1 = selu_f(c[nt][1] + b1v);
        float x2 = selu_f(c[nt][2] + b0v);
        float x3 = selu_f(c[nt][3] + b1v);
        xr[nt][0] = x0; xr[nt][1] = x1; xr[nt][2] = x2; xr[nt][3] = x3;
        if (nt < 4) { s0g += fabsf(x0) + fabsf(x1); s0h += fabsf(x2) + fabsf(x3); }
        else        { s1g += fabsf(x0) + fabsf(x1); s1h += fabsf(x2) + fabsf(x3); }
    }
    // reduce each head-sum across the 4-lane quad (k-lanes tq=0..3)
    s0g += __shfl_xor_sync(0xFFFFFFFF, s0g, 1);
    s0g += __shfl_xor_sync(0xFFFFFFFF, s0g, 2);
    s0h += __shfl_xor_sync(0xFFFFFFFF, s0h, 1);
    s0h += __shfl_xor_sync(0xFFFFFFFF, s0h, 2);
    s1g += __shfl_xor_sync(0xFFFFFFFF, s1g, 1);
    s1g += __shfl_xor_sync(0xFFFFFFFF, s1g, 2);
    s1h += __shfl_xor_sync(0xFFFFFFFF, s1h, 1);
    s1h += __shfl_xor_sync(0xFFFFFFFF, s1h, 2);
    float inv0g = __fdividef(1.0f, fmaxf(s0g, 1e-12f));
    float inv0h = __fdividef(1.0f, fmaxf(s0h, 1e-12f));
    float inv1g = __fdividef(1.0f, fmaxf(s1g, 1e-12f));
    float inv1h = __fdividef(1.0f, fmaxf(s1h, 1e-12f));

    #pragma unroll
    for (int nt = 0; nt < 8; nt++) {
        float ig = (nt < 4) ? inv0g : inv1g;
        float ih = (nt < 4) ? inv0h : inv1h;
        int col = nt * 8 + 2 * tq;
        stg[(m0 + g) * 67 + col]         = xr[nt][0] * ig;   // sign(d)*|d|/l1 == d/l1
        stg[(m0 + g) * 67 + col + 1]     = xr[nt][1] * ig;
        stg[(m0 + g + 8) * 67 + col]     = xr[nt][2] * ih;
        stg[(m0 + g + 8) * 67 + col + 1] = xr[nt][3] * ih;
    }
    __syncthreads();

    // coalesced global stores: 128 rows x 25 float2 (head0 cols 0..24, head1 32..56)
    float* ob = out + (size_t)row0 * (HG * E_N) + band * 200 + hp * 50;
    for (int i = t; i < 128 * 25; i += 256) {
        int r = i / 25, c2 = i - r * 25;
        int oc0 = 2 * c2, oc1 = 2 * c2 + 1;
        int sc0 = oc0 + (oc0 >= E_N ? 7 : 0);
        int sc1 = oc1 + (oc1 >= E_N ? 7 : 0);
        float2 v = make_float2(stg[r * 67 + sc0], stg[r * 67 + sc1]);
        *(float2*)(ob + (size_t)r * (HG * E_N) + oc0) = v;   // 8B aligned
    }
}

// ---------------------------------------------------------------------------
extern "C" void kernel_launch(void* const* d_in, const int* in_sizes, int n_in,
                              void* d_out, int out_size) {
    const float* X     = (const float*)d_in[0];
    const float* W1    = (const float*)d_in[1];
    const float* b1    = (const float*)d_in[2];
    const float* W2    = (const float*)d_in[3];
    const float* b2    = (const float*)d_in[4];
    const float* gamma = (const float*)d_in[5];
    const float* beta  = (const float*)d_in[6];
    const float* Wh    = (const float*)d_in[7];
    const float* bh    = (const float*)d_in[8];
    float* out = (float*)d_out;

    cudaFuncSetAttribute(kernA, cudaFuncAttributeMaxDynamicSharedMemorySize, 25856);
    cudaFuncSetAttribute(kernC, cudaFuncAttributeMaxDynamicSharedMemorySize, 34592);

    kernA<<<1024, 128, 25856>>>(X, W1, b1, W2, b2);
    kernB<<<1, 256>>>(gamma, beta);
    kernW<<<NBAND, 256>>>(Wh);
    kernE<<<256, 128>>>();
    kernC<<<dim3(48, 256), 256, 34592>>>(bh, out);
}

// round 11
// speedup vs baseline: 1.7348x; 1.0056x over previous
#include <cuda_runtime.h>
#include <cuda_bf16.h>
#include <cstdint>

#define B_N   32768
#define FIN   64
#define HID   32
#define E_N   25
#define HG    96
#define NBAND 12
#define NT2   4        // row-tiles (128 rows each) per kernC block

typedef unsigned long long u64;
typedef unsigned int u32;

// scratch (static device globals — no allocation)
__device__ float g_h2[B_N * HID];            // 4 MB
__device__ float g_part[1024][2 * HID];
__device__ float g_scale[HID];
__device__ float g_shift[HID];
__device__ u32   g_esplit[B_N * 32];         // per row 128B = bf16[64]: hi k0..31 | lo k0..31
__device__ u32   g_wsplit[NBAND * 256 * 32]; // per band 256 B-rows x 128B (same hi|lo layout)

__device__ __forceinline__ float selu_f(float x) {
    float p = 1.0507009873554805f * x;
    float n = 1.7580993408473766f * (__expf(x) - 1.0f);
    return x > 0.0f ? p : n;
}
__device__ __forceinline__ u64 pk2(float lo, float hi) {
    u64 r;
    asm("mov.b64 %0, {%1,%2};" : "=l"(r)
        : "r"(__float_as_uint(lo)), "r"(__float_as_uint(hi)));
    return r;
}
__device__ __forceinline__ void upk2(u64 v, float& lo, float& hi) {
    u32 a, b;
    asm("mov.b64 {%0,%1}, %2;" : "=r"(a), "=r"(b) : "l"(v));
    lo = __uint_as_float(a); hi = __uint_as_float(b);
}
#define FFMA2(d, a, b) asm("fma.rn.f32x2 %0, %1, %2, %0;" : "+l"(d) : "l"(a), "l"(b))

__device__ __forceinline__ uint16_t bf16b(float x) {
    __nv_bfloat16 h = __float2bfloat16(x);
    return *(uint16_t*)&h;
}
__device__ __forceinline__ float bf16f(uint16_t b) {
    __nv_bfloat16 h = *(__nv_bfloat16*)&b;
    return (float)h;
}

// warp-level bf16 MMA (HMMA), sm_80+ baseline — compiles for compute_103
__device__ __forceinline__ void mma16816(float* c, const u32* a, u32 b0, u32 b1) {
    asm volatile(
        "mma.sync.aligned.m16n8k16.row.col.f32.bf16.bf16.f32 "
        "{%0,%1,%2,%3}, {%4,%5,%6,%7}, {%8,%9}, {%0,%1,%2,%3};"
        : "+f"(c[0]), "+f"(c[1]), "+f"(c[2]), "+f"(c[3])
        : "r"(a[0]), "r"(a[1]), "r"(a[2]), "r"(a[3]), "r"(b0), "r"(b1));
}

// ---------------------------------------------------------------------------
// Kernel A: h = selu(X@W1+b1); h2 = h@W2+b2; store h2 + BN partials
// ---------------------------------------------------------------------------
__global__ void __launch_bounds__(128, 8) kernA(
    const float* __restrict__ X,
    const float* __restrict__ W1, const float* __restrict__ b1,
    const float* __restrict__ W2, const float* __restrict__ b2)
{
    extern __shared__ char sm[];
    float* xs  = (float*)sm;
    float* w1s = (float*)(sm + 8704);
    float* w2s = (float*)(sm + 8704 + 8192);
    float* b1s = (float*)(sm + 8704 + 8192 + 4096);
    float* b2s = b1s + HID;
    float* hs  = (float*)(sm + 8704 + 8192 + 4096 + 256);

    int t = threadIdx.x;
    int rowbase = blockIdx.x * 32;
    const float* Xb = X + (size_t)rowbase * FIN;

    #pragma unroll
    for (int j = 0; j < 4; j++) {
        int idx = t + j * 128;
        float4 v = ((const float4*)Xb)[idx];
        int row = idx >> 4, col = (idx & 15) * 4;
        *(float4*)&xs[row * 68 + col] = v;
    }
    #pragma unroll
    for (int j = 0; j < 4; j++) ((float4*)w1s)[t + j * 128] = ((const float4*)W1)[t + j * 128];
    #pragma unroll
    for (int j = 0; j < 2; j++) ((float4*)w2s)[t + j * 128] = ((const float4*)W2)[t + j * 128];
    if (t < HID) { b1s[t] = b1[t]; b2s[t] = b2[t]; }
    __syncthreads();

    int r  = t >> 2;
    int j0 = (t & 3) * 8;

    u64 acc[4];
    #pragma unroll
    for (int p = 0; p < 4; p++) acc[p] = *(const u64*)&b1s[j0 + 2 * p];
    #pragma unroll 8
    for (int k = 0; k < FIN; k++) {
        float xk = xs[r * 68 + k];
        u64 xv = pk2(xk, xk);
        ulonglong2 w0 = *(const ulonglong2*)&w1s[k * HID + j0];
        ulonglong2 w1v = *(const ulonglong2*)&w1s[k * HID + j0 + 4];
        FFMA2(acc[0], xv, w0.x);
        FFMA2(acc[1], xv, w0.y);
        FFMA2(acc[2], xv, w1v.x);
        FFMA2(acc[3], xv, w1v.y);
    }
    float hv[8];
    #pragma unroll
    for (int p = 0; p < 4; p++) {
        float a, b; upk2(acc[p], a, b);
        hv[2 * p] = selu_f(a); hv[2 * p + 1] = selu_f(b);
    }
    *(float4*)&hs[r * 36 + j0]     = make_float4(hv[0], hv[1], hv[2], hv[3]);
    *(float4*)&hs[r * 36 + j0 + 4] = make_float4(hv[4], hv[5], hv[6], hv[7]);
    __syncthreads();

    u64 acc2[4];
    #pragma unroll
    for (int p = 0; p < 4; p++) acc2[p] = *(const u64*)&b2s[j0 + 2 * p];
    #pragma unroll 8
    for (int k = 0; k < HID; k++) {
        float hk = hs[r * 36 + k];
        u64 hvv = pk2(hk, hk);
        ulonglong2 w0 = *(const ulonglong2*)&w2s[k * HID + j0];
        ulonglong2 w1v = *(const ulonglong2*)&w2s[k * HID + j0 + 4];
        FFMA2(acc2[0], hvv, w0.x);
        FFMA2(acc2[1], hvv, w0.y);
        FFMA2(acc2[2], hvv, w1v.x);
        FFMA2(acc2[3], hvv, w1v.y);
    }
    float o[8];
    #pragma unroll
    for (int p = 0; p < 4; p++) upk2(acc2[p], o[2 * p], o[2 * p + 1]);

    float* H2r = g_h2 + (size_t)(rowbase + r) * HID + j0;
    *(float4*)H2r       = make_float4(o[0], o[1], o[2], o[3]);
    *(float4*)(H2r + 4) = make_float4(o[4], o[5], o[6], o[7]);

    __syncthreads();
    *(float4*)&hs[r * 36 + j0]     = make_float4(o[0], o[1], o[2], o[3]);
    *(float4*)&hs[r * 36 + j0 + 4] = make_float4(o[4], o[5], o[6], o[7]);
    __syncthreads();

    if (t < HID) {
        float s = 0.f, s2 = 0.f;
        #pragma unroll 8
        for (int rr = 0; rr < 32; rr++) {
            float v = hs[rr * 36 + t];
            s += v; s2 += v * v;
        }
        g_part[blockIdx.x][t]       = s;
        g_part[blockIdx.x][HID + t] = s2;
    }
}

// ---------------------------------------------------------------------------
// Kernel B: fold partials -> scale/shift
// ---------------------------------------------------------------------------
__global__ void kernB(const float* __restrict__ gamma, const float* __restrict__ beta) {
    __shared__ float ps[8][64];
    int t = threadIdx.x;
    int c = t & 31, ch = t >> 5;
    float s = 0.f, s2 = 0.f;
    #pragma unroll 4
    for (int b = ch * 128; b < ch * 128 + 128; b++) {
        s  += g_part[b][c];
        s2 += g_part[b][HID + c];
    }
    ps[ch][c] = s; ps[ch][HID + c] = s2;
    __syncthreads();
    if (t < HID) {
        float S = 0.f, S2 = 0.f;
        #pragma unroll
        for (int ch2 = 0; ch2 < 8; ch2++) { S += ps[ch2][t]; S2 += ps[ch2][HID + t]; }
        float mu  = S  * (1.0f / B_N);
        float var = S2 * (1.0f / B_N) - mu * mu;
        float sc  = gamma[t] * rsqrtf(var + 1e-5f);
        g_scale[t] = sc;
        g_shift[t] = beta[t] - mu * sc;
    }
}

// ---------------------------------------------------------------------------
// Kernel E: e = selu(BN(h2)) -> bf16 hi/lo split -> g_esplit
// half-row per thread (4 q's = 64B of h2) -> 2x parallelism vs full-row
// ---------------------------------------------------------------------------
__global__ void __launch_bounds__(128) kernE() {
    int idx = blockIdx.x * 128 + threadIdx.x;     // 0 .. 2*B_N-1
    int row = idx >> 1;
    int qb  = (idx & 1) * 4;                      // q base: 0 or 4
    const float4* hp = (const float4*)(g_h2 + (size_t)row * HID);
    u32 wh[8], wl[8];
    #pragma unroll
    for (int qq = 0; qq < 4; qq++) {
        int q = qb + qq;
        float4 v = hp[q];
        float e0 = selu_f(fmaf(v.x, g_scale[4 * q + 0], g_shift[4 * q + 0]));
        float e1 = selu_f(fmaf(v.y, g_scale[4 * q + 1], g_shift[4 * q + 1]));
        float e2 = selu_f(fmaf(v.z, g_scale[4 * q + 2], g_shift[4 * q + 2]));
        float e3 = selu_f(fmaf(v.w, g_scale[4 * q + 3], g_shift[4 * q + 3]));
        uint16_t h0 = bf16b(e0), h1 = bf16b(e1), h2v = bf16b(e2), h3 = bf16b(e3);
        wh[2 * qq]     = (u32)h0 | ((u32)h1 << 16);
        wh[2 * qq + 1] = (u32)h2v | ((u32)h3 << 16);
        uint16_t l0 = bf16b(e0 - bf16f(h0)), l1 = bf16b(e1 - bf16f(h1));
        uint16_t l2 = bf16b(e2 - bf16f(h2v)), l3 = bf16b(e3 - bf16f(h3));
        wl[2 * qq]     = (u32)l0 | ((u32)l1 << 16);
        wl[2 * qq + 1] = (u32)l2 | ((u32)l3 << 16);
    }
    uint4* op = (uint4*)g_esplit + (size_t)row * 8;
    int hb = qb >> 1;   // 0 or 2
    op[hb]     = make_uint4(wh[0], wh[1], wh[2], wh[3]);
    op[hb + 1] = make_uint4(wh[4], wh[5], wh[6], wh[7]);
    op[4 + hb]     = make_uint4(wl[0], wl[1], wl[2], wl[3]);
    op[4 + hb + 1] = make_uint4(wl[4], wl[5], wl[6], wl[7]);
}

// ---------------------------------------------------------------------------
// Kernel W: weight bf16 hi/lo split -> g_wsplit  (B-row = hgl*32 + j, j>=25 zero)
// ---------------------------------------------------------------------------
__global__ void __launch_bounds__(256) kernW(const float* __restrict__ Wh) {
    int band = blockIdx.x;
    int t = threadIdx.x;
    int hgl = t >> 5, j = t & 31;
    u32 w[32];
    #pragma unroll
    for (int i = 0; i < 32; i++) w[i] = 0u;
    if (j < E_N) {
        const float* src = Wh + ((size_t)(band * 8 + hgl) * HID) * E_N + j;
        #pragma unroll
        for (int ww = 0; ww < 16; ww++) {
            float v0 = src[(2 * ww) * E_N];
            float v1 = src[(2 * ww + 1) * E_N];
            uint16_t h0 = bf16b(v0), h1 = bf16b(v1);
            w[ww] = (u32)h0 | ((u32)h1 << 16);
            uint16_t l0 = bf16b(v0 - bf16f(h0)), l1 = bf16b(v1 - bf16f(h1));
            w[16 + ww] = (u32)l0 | ((u32)l1 << 16);
        }
    }
    uint4* dst = (uint4*)g_wsplit + ((size_t)band * 256 + t) * 8;
    #pragma unroll
    for (int q = 0; q < 8; q++)
        dst[q] = make_uint4(w[4 * q], w[4 * q + 1], w[4 * q + 2], w[4 * q + 3]);
}

// ---------------------------------------------------------------------------
// Kernel C: D = e-split x w-split via mma.sync bf16 (hi*hi + hi*lo + lo*hi),
// bias + SELU + per-head L1-normalize, compact staging -> coalesced stores.
// grid (48 head-pairs, 64) x 256 threads; NT2=4 row-tiles of 128 per block.
// B tile (2 heads, 64 padded n-rows) + bias persist across tiles.
// smem: B[64][144B] @0 | bhs[64]f @9216 | A[128][144B] @9472 (stg[64][68]f aliases A)
// ---------------------------------------------------------------------------
__global__ void __launch_bounds__(256, 3) kernC(const float* __restrict__ bh,
                                                float* __restrict__ out)
{
    extern __shared__ char sm[];
    u32* Bs32  = (u32*)sm;               // row stride 36 u32
    float* bhs = (float*)(sm + 9216);    // [64]
    u32* As32  = (u32*)(sm + 9472);      // row stride 36 u32
    float* stg = (float*)(sm + 9472);    // [64][68] alias over A (post-MMA)

    int t = threadIdx.x;
    int wid = t >> 5, lane = t & 31;
    int g = lane >> 2, tq = lane & 3;
    int band = blockIdx.x >> 2, hp = blockIdx.x & 3;
    int m0 = wid * 16;
    int halfw = wid >> 2;                // which 64-row half this warp's rows are in
    int lr0 = (m0 & 63) + g;             // local row within half

    // B fill (once): 64 rows x 8 uint4
    {
        const uint4* srcB = (const uint4*)g_wsplit + ((size_t)band * 256 + hp * 64) * 8;
        #pragma unroll
        for (int i = t; i < 512; i += 256) {
            int r = i >> 3, j = i & 7;
            *(uint4*)(sm + r * 144 + j * 16) = srcB[i];
        }
    }
    if (t < 64) {
        int hh = t >> 5, j = t & 31;
        int head = band * 8 + hp * 2 + hh;
        bhs[t] = (j < E_N) ? bh[head * E_N + j] : 0.0f;
    }

    int row0 = blockIdx.y * (NT2 * 128);
    for (int tile = 0; tile < NT2; tile++) {
        // A fill: 128 rows x 8 uint4 (prev tile's stg reads done at loop-end sync)
        {
            const uint4* srcA = (const uint4*)g_esplit + (size_t)row0 * 8;
            #pragma unroll
            for (int i = t; i < 1024; i += 256) {
                int r = i >> 3, j = i & 7;
                *(uint4*)(sm + 9472 + r * 144 + j * 16) = srcA[i];
            }
        }
        __syncthreads();   // A (+ B/bias on tile 0) visible

        // A fragments: 4 k-blocks of 16 (kb 0,1 = hi; 2,3 = lo); conflict-free
        u32 aa[4][4];
        #pragma unroll
        for (int kb = 0; kb < 4; kb++) {
            int base = kb * 8 + tq;
            aa[kb][0] = As32[(m0 + g) * 36 + base];
            aa[kb][1] = As32[(m0 + g + 8) * 36 + base];
            aa[kb][2] = As32[(m0 + g) * 36 + base + 4];
            aa[kb][3] = As32[(m0 + g + 8) * 36 + base + 4];
        }

        float c[8][4];
        #pragma unroll
        for (int nt = 0; nt < 8; nt++)
            #pragma unroll
            for (int q = 0; q < 4; q++) c[nt][q] = 0.0f;

        #pragma unroll
        for (int nt = 0; nt < 8; nt++) {
            int nb = (nt * 8 + g) * 36 + tq;
            u32 b00 = Bs32[nb],      b01 = Bs32[nb + 4];
            u32 b10 = Bs32[nb + 8],  b11 = Bs32[nb + 12];
            u32 b20 = Bs32[nb + 16], b21 = Bs32[nb + 20];
            u32 b30 = Bs32[nb + 24], b31 = Bs32[nb + 28];
            mma16816(c[nt], aa[0], b00, b01);   // hi*hi
            mma16816(c[nt], aa[1], b10, b11);
            mma16816(c[nt], aa[0], b20, b21);   // hi*lo
            mma16816(c[nt], aa[1], b30, b31);
            mma16816(c[nt], aa[2], b00, b01);   // lo*hi
            mma16816(c[nt], aa[3], b10, b11);
        }
        __syncthreads();   // all A smem reads done -> stg may overwrite A

        // epilogue IN PLACE: bias + selu + per-head abs row sums
        float s0g = 0.f, s0h = 0.f, s1g = 0.f, s1h = 0.f;
        #pragma unroll
        for (int nt = 0; nt < 8; nt++) {
            float b0v = bhs[nt * 8 + 2 * tq];
            float b1v = bhs[nt * 8 + 2 * tq + 1];
            c[nt][0] = selu_f(c[nt][0] + b0v);
            c[nt][1] = selu_f(c[nt][1] + b1v);
            c[nt][2] = selu_f(c[nt][2] + b0v);
            c[nt][3] = selu_f(c[nt][3] + b1v);
            if (nt < 4) { s0g += fabsf(c[nt][0]) + fabsf(c[nt][1]);
                          s0h += fabsf(c[nt][2]) + fabsf(c[nt][3]); }
            else        { s1g += fabsf(c[nt][0]) + fabsf(c[nt][1]);
                          s1h += fabsf(c[nt][2]) + fabsf(c[nt][3]); }
        }
        s0g += __shfl_xor_sync(0xFFFFFFFF, s0g, 1);
        s0g += __shfl_xor_sync(0xFFFFFFFF, s0g, 2);
        s0h += __shfl_xor_sync(0xFFFFFFFF, s0h, 1);
        s0h += __shfl_xor_sync(0xFFFFFFFF, s0h, 2);
        s1g += __shfl_xor_sync(0xFFFFFFFF, s1g, 1);
        s1g += __shfl_xor_sync(0xFFFFFFFF, s1g, 2);
        s1h += __shfl_xor_sync(0xFFFFFFFF, s1h, 1);
        s1h += __shfl_xor_sync(0xFFFFFFFF, s1h, 2);
        float inv0g = __fdividef(1.0f, fmaxf(s0g, 1e-12f));
        float inv0h = __fdividef(1.0f, fmaxf(s0h, 1e-12f));
        float inv1g = __fdividef(1.0f, fmaxf(s1g, 1e-12f));
        float inv1h = __fdividef(1.0f, fmaxf(s1h, 1e-12f));
        #pragma unroll
        for (int nt = 0; nt < 8; nt++) {
            float ig = (nt < 4) ? inv0g : inv1g;
            float ih = (nt < 4) ? inv0h : inv1h;
            c[nt][0] *= ig; c[nt][1] *= ig;    // sign(d)*|d|/l1 == d/l1
            c[nt][2] *= ih; c[nt][3] *= ih;
        }

        // two 64-row halves: owning warps stage compact (head1 at col 25), all store
        #pragma unroll
        for (int half = 0; half < 2; half++) {
            if (halfw == half) {
                #pragma unroll
                for (int nt = 0; nt < 8; nt++) {
                    int ncol = nt * 8 + 2 * tq;
                    int bj   = (nt < 4) ? ncol : (ncol - 32);
                    int dcol = (nt < 4) ? ncol : (E_N + (ncol - 32));
                    if (bj < E_N) {
                        stg[lr0 * 68 + dcol]       = c[nt][0];
                        stg[(lr0 + 8) * 68 + dcol] = c[nt][2];
                    }
                    if (bj + 1 < E_N) {
                        stg[lr0 * 68 + dcol + 1]       = c[nt][1];
                        stg[(lr0 + 8) * 68 + dcol + 1] = c[nt][3];
                    }
                }
            }
            __syncthreads();
            float* ob = out + (size_t)(row0 + 64 * half) * (HG * E_N)
                            + band * 200 + hp * 50;
            for (int i = t; i < 64 * 25; i += 256) {
                int r = i / 25, c2 = i - r * 25;
                float2 v = make_float2(stg[r * 68 + 2 * c2], stg[r * 68 + 2 * c2 + 1]);
                *(float2*)(ob + (size_t)r * (HG * E_N) + 2 * c2) = v;   // 8B aligned
            }
            __syncthreads();
        }
        row0 += 128;
    }
}

// ---------------------------------------------------------------------------
extern "C" void kernel_launch(void* const* d_in, const int* in_sizes, int n_in,
                              void* d_out, int out_size) {
    const float* X     = (const float*)d_in[0];
    const float* W1    = (const float*)d_in[1];
    const float* b1    = (const float*)d_in[2];
    const float* W2    = (const float*)d_in[3];
    const float* b2    = (const float*)d_in[4];
    const float* gamma = (const float*)d_in[5];
    const float* beta  = (const float*)d_in[6];
    const float* Wh    = (const float*)d_in[7];
    const float* bh    = (const float*)d_in[8];
    float* out = (float*)d_out;

    cudaFuncSetAttribute(kernA, cudaFuncAttributeMaxDynamicSharedMemorySize, 25856);
    cudaFuncSetAttribute(kernC, cudaFuncAttributeMaxDynamicSharedMemorySize, 27904);

    kernA<<<1024, 128, 25856>>>(X, W1, b1, W2, b2);
    kernB<<<1, 256>>>(gamma, beta);
    kernW<<<NBAND, 256>>>(Wh);
    kernE<<<512, 128>>>();
    kernC<<<dim3(48, 64), 256, 27904>>>(bh, out);
}